// round 1
// baseline (speedup 1.0000x reference)
#include <cuda_runtime.h>

// Trilinear resize: [4,128,128,128,2] f32 -> [4,192,192,192,2] f32 (zoom 1.5/axis)
// One output voxel (both channels, a float2) per thread. Fused 3D gather of the
// 8 corner voxels; weight math replicates the reference (loc = i/1.5, floor,
// clip, w0 = i1 - clip(loc)).

#define IN_D  128
#define OUT_D 192
#define OUT_VOX (4 * OUT_D * OUT_D * OUT_D)   // 28,311,552 output voxels

struct AxisMap {
    int i0, i1;
    float w0, w1;
};

__device__ __forceinline__ AxisMap axis_map(int i) {
    // loc = i / 1.5 (reference divides by zoom)
    float loc = (float)i / 1.5f;
    int fi = (int)loc;                 // loc >= 0, so trunc == floor
    AxisMap m;
    m.i0 = min(fi, IN_D - 1);
    m.i1 = min(m.i0 + 1, IN_D - 1);
    float cl = fminf(loc, (float)(IN_D - 1));
    m.w0 = (float)m.i1 - cl;
    m.w1 = 1.0f - m.w0;
    return m;
}

__global__ __launch_bounds__(256) void resize_trilinear_kernel(
    const float2* __restrict__ in,   // [4,128,128,128] voxels of float2
    float2* __restrict__ out)        // [4,192,192,192] voxels of float2
{
    int idx = blockIdx.x * blockDim.x + threadIdx.x;
    if (idx >= OUT_VOX) return;

    int x = idx % OUT_D;
    int t = idx / OUT_D;
    int y = t % OUT_D;
    t /= OUT_D;
    int z = t % OUT_D;
    int b = t / OUT_D;

    AxisMap mx = axis_map(x);
    AxisMap my = axis_map(y);
    AxisMap mz = axis_map(z);

    const float2* base = in + (long long)b * (IN_D * IN_D * IN_D);

    const float2* pz0 = base + (long long)mz.i0 * (IN_D * IN_D);
    const float2* pz1 = base + (long long)mz.i1 * (IN_D * IN_D);

    const float2* p00 = pz0 + my.i0 * IN_D;
    const float2* p01 = pz0 + my.i1 * IN_D;
    const float2* p10 = pz1 + my.i0 * IN_D;
    const float2* p11 = pz1 + my.i1 * IN_D;

    float2 c000 = __ldg(p00 + mx.i0);
    float2 c001 = __ldg(p00 + mx.i1);
    float2 c010 = __ldg(p01 + mx.i0);
    float2 c011 = __ldg(p01 + mx.i1);
    float2 c100 = __ldg(p10 + mx.i0);
    float2 c101 = __ldg(p10 + mx.i1);
    float2 c110 = __ldg(p11 + mx.i0);
    float2 c111 = __ldg(p11 + mx.i1);

    // lerp along x
    float a00x = c000.x * mx.w0 + c001.x * mx.w1;
    float a00y = c000.y * mx.w0 + c001.y * mx.w1;
    float a01x = c010.x * mx.w0 + c011.x * mx.w1;
    float a01y = c010.y * mx.w0 + c011.y * mx.w1;
    float a10x = c100.x * mx.w0 + c101.x * mx.w1;
    float a10y = c100.y * mx.w0 + c101.y * mx.w1;
    float a11x = c110.x * mx.w0 + c111.x * mx.w1;
    float a11y = c110.y * mx.w0 + c111.y * mx.w1;

    // lerp along y
    float b0x = a00x * my.w0 + a01x * my.w1;
    float b0y = a00y * my.w0 + a01y * my.w1;
    float b1x = a10x * my.w0 + a11x * my.w1;
    float b1y = a10y * my.w0 + a11y * my.w1;

    // lerp along z
    float2 r;
    r.x = b0x * mz.w0 + b1x * mz.w1;
    r.y = b0y * mz.w0 + b1y * mz.w1;

    out[idx] = r;
}

extern "C" void kernel_launch(void* const* d_in, const int* in_sizes, int n_in,
                              void* d_out, int out_size) {
    const float2* in = (const float2*)d_in[0];
    float2* out = (float2*)d_out;

    int threads = 256;
    int blocks = (OUT_VOX + threads - 1) / threads;   // 110592
    resize_trilinear_kernel<<<blocks, threads>>>(in, out);
}

// round 2
// speedup vs baseline: 1.7143x; 1.7143x over previous
#include <cuda_runtime.h>

// Trilinear resize [4,128,128,128,2] f32 -> [4,192,192,192,2] f32, zoom=1.5.
// Exploits exact 3-out-per-2-in periodicity: each thread produces a 3x3x3
// output micro-block from a 3x3x3 input micro-block with fixed weights
// {1, 1/3, 2/3} per axis (offset 0 is an exact copy).

#define IN_D   128
#define OUT_D  192
#define KBLK   64                       // micro-blocks per axis (192/3)
#define NBLK   (4 * KBLK * KBLK * KBLK) // 1,048,576 micro-blocks

__global__ __launch_bounds__(256) void resize_micro3_kernel(
    const float2* __restrict__ in,   // [4,128,128,128] voxels (C=2 packed)
    float2* __restrict__ out)        // [4,192,192,192] voxels
{
    int idx = blockIdx.x * 256 + threadIdx.x;
    if (idx >= NBLK) return;

    int xk = idx & 63;
    int yk = (idx >> 6) & 63;
    int zk = (idx >> 12) & 63;
    int b  = idx >> 18;

    const int x0 = 2 * xk;
    const int y0 = 2 * yk;
    const int z0 = 2 * zk;
    // third input index, clamped at the volume edge (xk=63 -> 128 -> 127)
    const int x2 = min(x0 + 2, IN_D - 1);
    const int y2 = min(y0 + 2, IN_D - 1);
    const int z2 = min(z0 + 2, IN_D - 1);

    const float c13 = 1.0f / 3.0f;
    const float c23 = 2.0f / 3.0f;

    const float2* base = in + (size_t)b * (IN_D * IN_D * IN_D);

    // p[zi][yo][xo]: x- and y-lerped values for the 3 input z-planes
    float2 p[3][3][3];

    #pragma unroll
    for (int zi = 0; zi < 3; zi++) {
        int z = (zi < 2) ? (z0 + zi) : z2;
        const float2* pz = base + (size_t)z * (IN_D * IN_D);

        float2 row[3][3];   // [yin][xo] x-lerped
        #pragma unroll
        for (int yi = 0; yi < 3; yi++) {
            int y = (yi < 2) ? (y0 + yi) : y2;
            const float2* pr = pz + y * IN_D;
            float2 a0 = __ldg(pr + x0);
            float2 a1 = __ldg(pr + x0 + 1);
            float2 a2 = __ldg(pr + x2);
            row[yi][0] = a0;  // weight {1, 0}: exact copy
            row[yi][1] = make_float2(fmaf(a0.x, c13, a1.x * c23),
                                     fmaf(a0.y, c13, a1.y * c23));
            row[yi][2] = make_float2(fmaf(a1.x, c23, a2.x * c13),
                                     fmaf(a1.y, c23, a2.y * c13));
        }

        #pragma unroll
        for (int xo = 0; xo < 3; xo++) {
            p[zi][0][xo] = row[0][xo];
            p[zi][1][xo] = make_float2(
                fmaf(row[0][xo].x, c13, row[1][xo].x * c23),
                fmaf(row[0][xo].y, c13, row[1][xo].y * c23));
            p[zi][2][xo] = make_float2(
                fmaf(row[1][xo].x, c23, row[2][xo].x * c13),
                fmaf(row[1][xo].y, c23, row[2][xo].y * c13));
        }
    }

    // z-lerp + store 3x3x3 outputs
    const int ox = 3 * xk;
    const int oy = 3 * yk;
    const int oz = 3 * zk;

    #pragma unroll
    for (int zo = 0; zo < 3; zo++) {
        size_t zb = (((size_t)b * OUT_D + (oz + zo)) * OUT_D + oy) * OUT_D + ox;
        #pragma unroll
        for (int yo = 0; yo < 3; yo++) {
            float2* orow = out + zb + (size_t)yo * OUT_D;
            #pragma unroll
            for (int xo = 0; xo < 3; xo++) {
                float2 v;
                if (zo == 0) {
                    v = p[0][yo][xo];
                } else if (zo == 1) {
                    v = make_float2(
                        fmaf(p[0][yo][xo].x, c13, p[1][yo][xo].x * c23),
                        fmaf(p[0][yo][xo].y, c13, p[1][yo][xo].y * c23));
                } else {
                    v = make_float2(
                        fmaf(p[1][yo][xo].x, c23, p[2][yo][xo].x * c13),
                        fmaf(p[1][yo][xo].y, c23, p[2][yo][xo].y * c13));
                }
                orow[xo] = v;
            }
        }
    }
}

extern "C" void kernel_launch(void* const* d_in, const int* in_sizes, int n_in,
                              void* d_out, int out_size) {
    const float2* in = (const float2*)d_in[0];
    float2* out = (float2*)d_out;

    int threads = 256;
    int blocks = (NBLK + threads - 1) / threads;  // 4096
    resize_micro3_kernel<<<blocks, threads>>>(in, out);
}

// round 3
// speedup vs baseline: 3.1811x; 1.8556x over previous
#include <cuda_runtime.h>

// Trilinear resize [4,128,128,128,2] f32 -> [4,192,192,192,2] f32, zoom=1.5.
// zoom=1.5 is exactly 3 outputs per 2 inputs with fixed weights {1, 1/3, 2/3}.
// Block = (b, zk, yk): loads input strip [3z][3y][128x] into smem (coalesced),
// each thread owns one output x column and produces the 3x3 (y,z) outputs for
// it in registers, storing 9 perfectly coalesced 192-wide output rows.

#define IN_D  128
#define OUT_D 192

__global__ __launch_bounds__(192) void resize_smem_kernel(
    const float2* __restrict__ in,   // [4,128,128,128] voxels (C=2 packed)
    float2* __restrict__ out)        // [4,192,192,192] voxels
{
    __shared__ float2 tile[9][IN_D];   // [zi*3+yi][x], 9216 B

    const int blk = blockIdx.x;
    const int yk = blk & 63;
    const int zk = (blk >> 6) & 63;
    const int b  = blk >> 12;

    const int tid = threadIdx.x;       // 0..191

    const float2* base = in + (size_t)b * (IN_D * IN_D * IN_D);

    // ---- Phase 1: cooperative coalesced load of 9 input rows (1152 float2) ----
    #pragma unroll
    for (int i = 0; i < 6; i++) {
        int idx = i * 192 + tid;       // 0..1151
        int x = idx & 127;
        int r = idx >> 7;              // 0..8
        int zi = r / 3;
        int yi = r - 3 * zi;
        int z = min(2 * zk + zi, IN_D - 1);
        int y = min(2 * yk + yi, IN_D - 1);
        tile[r][x] = __ldg(base + ((size_t)z * IN_D + y) * IN_D + x);
    }
    __syncthreads();

    // ---- Phase 2: per-thread x-lerp, then y/z lerp in registers ----
    const float c13 = 1.0f / 3.0f;
    const float c23 = 2.0f / 3.0f;

    const int k  = tid / 3;            // output micro-block index along x
    const int xo = tid - 3 * k;        // 0,1,2 within micro-block

    // corner indices + weights for this output x
    int xA, xB;
    float wA;
    if (xo == 0)      { xA = 2 * k;     xB = xA;                     wA = 1.0f; }
    else if (xo == 1) { xA = 2 * k;     xB = 2 * k + 1;              wA = c13;  }
    else              { xA = 2 * k + 1; xB = min(2 * k + 2, IN_D-1); wA = c23;  }
    const float wB = 1.0f - wA;

    float2 xl[9];                      // x-lerped, [zi*3+yi]
    #pragma unroll
    for (int r = 0; r < 9; r++) {
        float2 a = tile[r][xA];
        float2 c = tile[r][xB];
        xl[r] = make_float2(fmaf(a.x, wA, c.x * wB),
                            fmaf(a.y, wA, c.y * wB));
    }

    // y-lerp: per z-plane, 3 input y -> 3 output y
    float2 yl[3][3];                   // [zi][yo]
    #pragma unroll
    for (int zi = 0; zi < 3; zi++) {
        float2 v0 = xl[3 * zi + 0];
        float2 v1 = xl[3 * zi + 1];
        float2 v2 = xl[3 * zi + 2];
        yl[zi][0] = v0;
        yl[zi][1] = make_float2(fmaf(v0.x, c13, v1.x * c23),
                                fmaf(v0.y, c13, v1.y * c23));
        yl[zi][2] = make_float2(fmaf(v1.x, c23, v2.x * c13),
                                fmaf(v1.y, c23, v2.y * c13));
    }

    // z-lerp + coalesced stores (thread t writes column t of each 192-row)
    size_t obase = (((size_t)b * OUT_D + 3 * zk) * OUT_D + 3 * yk) * OUT_D + tid;
    #pragma unroll
    for (int yo = 0; yo < 3; yo++) {
        float2 v0 = yl[0][yo];
        float2 v1 = yl[1][yo];
        float2 v2 = yl[2][yo];
        out[obase + (size_t)(0 * OUT_D + yo) * OUT_D] = v0;
        out[obase + (size_t)(1 * OUT_D + yo) * OUT_D] =
            make_float2(fmaf(v0.x, c13, v1.x * c23),
                        fmaf(v0.y, c13, v1.y * c23));
        out[obase + (size_t)(2 * OUT_D + yo) * OUT_D] =
            make_float2(fmaf(v1.x, c23, v2.x * c13),
                        fmaf(v1.y, c23, v2.y * c13));
    }
}

extern "C" void kernel_launch(void* const* d_in, const int* in_sizes, int n_in,
                              void* d_out, int out_size) {
    const float2* in = (const float2*)d_in[0];
    float2* out = (float2*)d_out;

    int blocks = 4 * 64 * 64;   // (b, zk, yk) = 16384
    resize_smem_kernel<<<blocks, 192>>>(in, out);
}